// round 17
// baseline (speedup 1.0000x reference)
#include <cuda_runtime.h>
#include <cuda_fp16.h>
#include <math.h>
#include <stdint.h>

#define T_SEQ  2048
#define DIM_C  2048
#define NH     16
#define HD     128
#define QKV_N  6144      // 3 * 2048, row layout [t][e*2048 + h*128 + d]
#define ATTN_SCALE 0.12f

// Scratch
__device__ __half g_qkvh[(size_t)T_SEQ * QKV_N];       // 25 MB (fp16 q/k/v)
__device__ __half g_xh[(size_t)T_SEQ * DIM_C];         // 8 MB
__device__ __half g_wh[(size_t)4 * DIM_C * DIM_C];     // 32 MB
__device__ __half g_yh[(size_t)T_SEQ * DIM_C];         // 8 MB

// ---------------------------------------------------------------------------
// helpers
// ---------------------------------------------------------------------------
__device__ __forceinline__ void mma_f16(float* d, const unsigned* a, const unsigned* b) {
    asm volatile(
        "mma.sync.aligned.m16n8k16.row.col.f32.f16.f16.f32 "
        "{%0,%1,%2,%3}, {%4,%5,%6,%7}, {%8,%9}, {%0,%1,%2,%3};\n"
        : "+f"(d[0]), "+f"(d[1]), "+f"(d[2]), "+f"(d[3])
        : "r"(a[0]), "r"(a[1]), "r"(a[2]), "r"(a[3]),
          "r"(b[0]), "r"(b[1]));
}

__device__ __forceinline__ unsigned smem_u32(const void* p) {
    return (unsigned)__cvta_generic_to_shared(p);
}

__device__ __forceinline__ unsigned h2u(__half2 h) {
    return *(unsigned*)&h;
}

__device__ __forceinline__ void ldsm4u(unsigned* u, unsigned addr) {
    asm volatile("ldmatrix.sync.aligned.m8n8.x4.shared.b16 {%0,%1,%2,%3}, [%4];"
                 : "=r"(u[0]), "=r"(u[1]), "=r"(u[2]), "=r"(u[3]) : "r"(addr));
}
__device__ __forceinline__ void ldsm4t(unsigned* u, unsigned addr) {
    asm volatile("ldmatrix.sync.aligned.m8n8.x4.trans.shared.b16 {%0,%1,%2,%3}, [%4];"
                 : "=r"(u[0]), "=r"(u[1]), "=r"(u[2]), "=r"(u[3]) : "r"(addr));
}

#define CP16(dst, src) \
    asm volatile("cp.async.cg.shared.global [%0], [%1], 16;" :: "r"(dst), "l"(src))
#define CPCOMMIT() asm volatile("cp.async.commit_group;")
#define CPWAIT1()  asm volatile("cp.async.wait_group 1;" ::: "memory")
#define CPWAIT0()  asm volatile("cp.async.wait_group 0;" ::: "memory")

// ---------------------------------------------------------------------------
// float -> half conversion (x, w; once)
// ---------------------------------------------------------------------------
__global__ void to_half_kernel(const float4* __restrict__ src,
                               __half2* __restrict__ dst, int n4)
{
    for (int i = blockIdx.x * blockDim.x + threadIdx.x; i < n4;
         i += gridDim.x * blockDim.x) {
        float4 v = src[i];
        dst[2 * i]     = __floats2half2_rn(v.x, v.y);
        dst[2 * i + 1] = __floats2half2_rn(v.z, v.w);
    }
}

// ---------------------------------------------------------------------------
// fp16 GEMM (TN) — proven in R16. fuse==1: fused RMSNorm+RoPE / v-blend
// epilogue writes fp16 q/k/v into g_qkvh.
// ---------------------------------------------------------------------------
#define HSPAD   72                  // halves per row (144 B)
#define HSTG    (128 * HSPAD)
#define GSTAGES 3
#define GEMM_SMEM (GSTAGES * 2 * HSTG * 2)   // 110,592 B

__global__ __launch_bounds__(256, 2)
void gemm_f16_kernel(const __half* __restrict__ A,
                     const __half* __restrict__ B,
                     float* __restrict__ C,
                     int M, int N, int K, int fuse,
                     const float* __restrict__ ve,
                     const float* __restrict__ lam)
{
    extern __shared__ float smg[];
    __half* As = (__half*)smg;                 // [3][128][72]
    __half* Bs = As + GSTAGES * HSTG;

    const int tid  = threadIdx.x;
    const int lane = tid & 31;
    const int wid  = tid >> 5;
    const int g    = lane >> 2;
    const int tig  = lane & 3;
    const int wm   = (wid & 1) * 64;
    const int wn   = (wid >> 1) * 32;

    const int rowBase = blockIdx.y * 128;
    const int colBase = blockIdx.x * 128;
    const __half* Ag = A + (size_t)rowBase * K;
    const __half* Bg = B + (size_t)colBase * K;

    const int arow = (lane & 7) + ((lane >> 3) & 1) * 8;
    const int acol = (lane >> 4) * 8;
    const int tl   = lane >> 3;
    const int brow = (lane & 7) + (tl >> 1) * 8;
    const int bcol = (tl & 1) * 8;

    unsigned aAddr[4], bAddr[2];
#pragma unroll
    for (int mi = 0; mi < 4; mi++)
        aAddr[mi] = smem_u32(&As[(wm + mi * 16 + arow) * HSPAD + acol]);
#pragma unroll
    for (int p = 0; p < 2; p++)
        bAddr[p] = smem_u32(&Bs[(wn + p * 16 + brow) * HSPAD + bcol]);

    const unsigned asA = smem_u32(As);
    const unsigned asB = smem_u32(Bs);
    const unsigned STGB = HSTG * 2;

    float acc[4][4][4];
#pragma unroll
    for (int mi = 0; mi < 4; mi++)
#pragma unroll
        for (int ni = 0; ni < 4; ni++)
#pragma unroll
            for (int c = 0; c < 4; c++) acc[mi][ni][c] = 0.0f;

    const int nk = K >> 6;

#define H_LOAD(chunk, stage)                                                   \
    do {                                                                       \
        const unsigned so = (unsigned)(stage) * STGB;                          \
        const size_t kh = (size_t)(chunk) * 64;                                \
        _Pragma("unroll")                                                      \
        for (int j = 0; j < 4; j++) {                                          \
            int f = tid + 256 * j;                                             \
            int row = f >> 3;                                                  \
            int seg = (f & 7) << 4;                                            \
            CP16(asA + so + (unsigned)(row * 144 + seg),                       \
                 (const char*)(Ag + (size_t)row * K + kh) + seg);              \
            CP16(asB + so + (unsigned)(row * 144 + seg),                       \
                 (const char*)(Bg + (size_t)row * K + kh) + seg);              \
        }                                                                      \
        CPCOMMIT();                                                            \
    } while (0)

    H_LOAD(0, 0);
    H_LOAD(1, 1);

    int slot = 0;
    for (int kt = 0; kt < nk; kt++) {
        CPWAIT1();
        __syncthreads();

        if (kt + GSTAGES - 1 < nk) {
            H_LOAD(kt + GSTAGES - 1, (kt + GSTAGES - 1) % GSTAGES);
        } else {
            CPCOMMIT();
        }

        const unsigned cOff = (unsigned)slot * STGB;
#pragma unroll
        for (int ks = 0; ks < 4; ks++) {
            const unsigned kOff = cOff + ks * 32;
            unsigned a[4][4], bq[2][4];
#pragma unroll
            for (int mi = 0; mi < 4; mi++) ldsm4u(a[mi], aAddr[mi] + kOff);
#pragma unroll
            for (int p = 0; p < 2; p++) ldsm4u(bq[p], bAddr[p] + kOff);
#pragma unroll
            for (int mi = 0; mi < 4; mi++)
#pragma unroll
                for (int p = 0; p < 2; p++) {
                    mma_f16(acc[mi][2 * p],     a[mi], &bq[p][0]);
                    mma_f16(acc[mi][2 * p + 1], a[mi], &bq[p][2]);
                }
        }
        slot = (slot + 1 == GSTAGES) ? 0 : slot + 1;
    }
#undef H_LOAD

    if (!fuse) {
        float* Cp = C + (size_t)rowBase * N + colBase;
#pragma unroll
        for (int mi = 0; mi < 4; mi++) {
            int m = wm + mi * 16 + g;
#pragma unroll
            for (int ni = 0; ni < 4; ni++) {
                int n = wn + ni * 8 + tig * 2;
                *(float2*)&Cp[(size_t)m * N + n] =
                    make_float2(acc[mi][ni][0], acc[mi][ni][1]);
                *(float2*)&Cp[(size_t)(m + 8) * N + n] =
                    make_float2(acc[mi][ni][2], acc[mi][ni][3]);
            }
        }
        return;
    }

    // fused epilogue: RMSNorm + RoPE / v-blend -> fp16 g_qkvh
    __syncthreads();
    float* Cs = smg;                 // [128][132]
#pragma unroll
    for (int mi = 0; mi < 4; mi++) {
        int m = wm + mi * 16 + g;
#pragma unroll
        for (int ni = 0; ni < 4; ni++) {
            int n = wn + ni * 8 + tig * 2;
            *(float2*)&Cs[m * 132 + n] =
                make_float2(acc[mi][ni][0], acc[mi][ni][1]);
            *(float2*)&Cs[(m + 8) * 132 + n] =
                make_float2(acc[mi][ni][2], acc[mi][ni][3]);
        }
    }
    __syncthreads();

    const int e = colBase >> 11;               // 0=q 1=k 2=v
    const float lam0 = (e == 2) ? lam[0] : 0.0f;
    const float lam1 = (e == 2) ? lam[1] : 0.0f;

    for (int rr = 0; rr < 16; rr++) {
        const int r = wid * 16 + rr;
        const int t = rowBase + r;
        float4 v = *(const float4*)&Cs[r * 132 + lane * 4];
        float ss = v.x * v.x + v.y * v.y + v.z * v.z + v.w * v.w;
#pragma unroll
        for (int o = 16; o > 0; o >>= 1)
            ss += __shfl_xor_sync(0xffffffffu, ss, o);
        const float rinv = rsqrtf(ss * (1.0f / 128.0f) + 1e-6f);

        float o4[4];
        const float* vp = (const float*)&v;
        if (e < 2) {
#pragma unroll
            for (int q = 0; q < 4; q++) {
                int c = lane * 4 + q;
                int j = c & 63;
                float cur = vp[q] * rinv;
                float par = Cs[r * 132 + (c ^ 64)] * rinv;
                float cs, sn;
                if (j < 32) {
                    float fr = exp2f((-10.0f / 31.0f) * (float)j);
                    float th = (float)t * fr;
                    cs = cosf(th); sn = sinf(th);
                } else { cs = 1.0f; sn = 0.0f; }
                o4[q] = (c < 64) ? (cur * cs + par * sn) : (cur * cs - par * sn);
            }
        } else {
            float4 vv = *(const float4*)(ve + (size_t)t * DIM_C +
                                         (colBase & 2047) + lane * 4);
            const float* vvp = (const float*)&vv;
#pragma unroll
            for (int q = 0; q < 4; q++)
                o4[q] = lam0 * (vp[q] * rinv) + lam1 * vvp[q];
        }
        __half2* dh = (__half2*)&g_qkvh[(size_t)t * QKV_N + colBase + lane * 4];
        dh[0] = __floats2half2_rn(o4[0], o4[1]);
        dh[1] = __floats2half2_rn(o4[2], o4[3]);
    }
}

// ---------------------------------------------------------------------------
// Causal flash attention v4 (fp16 mma): Q-tile 128, 8 warps x 16 rows (full
// 64 kv cols/warp). S C-fragment == PV A-fragment (no shuffles). V stored
// [s][d] row-major, B-fragments via ldmatrix.trans. K/V double-buffered via
// cp.async. ONE __syncthreads per KV tile. smem 104,448 B.
// ---------------------------------------------------------------------------
#define HPIT  136                      // halves per row (272 B)
#define KVH   (64 * HPIT)
#define AH_Q  0
#define AH_K  (128 * HPIT)
#define AH_V  (AH_K + 2 * KVH)
#define ATTN_SMEMH ((AH_V + 2 * KVH) * 2)   // 104,448 B

__global__ __launch_bounds__(256, 1)
void attn_kernel()
{
    extern __shared__ __half smh[];
    __half* Qs = smh + AH_Q;      // [128][136]
    __half* Ks = smh + AH_K;      // [2][64][136]
    __half* Vs = smh + AH_V;      // [2][64][136]

    const int h     = blockIdx.y;
    const int qt    = 15 - (int)blockIdx.x;
    const int qbase = qt * 128;
    const int tid   = threadIdx.x;
    const int lane  = tid & 31;
    const int wid   = tid >> 5;
    const int g     = lane >> 2;
    const int tig   = lane & 3;
    const int rw    = wid * 16;

    const int arow = (lane & 7) + ((lane >> 3) & 1) * 8;
    const int acol = (lane >> 4) * 8;
    const int tl   = lane >> 3;
    const int brow = (lane & 7) + (tl >> 1) * 8;   // K: [s][d]
    const int bcol = (tl & 1) * 8;
    const int vrow = (lane & 7) + (tl & 1) * 8;    // V trans: s rows
    const int vcol = (tl >> 1) * 8;

    const unsigned qAddr = smem_u32(&Qs[(rw + arow) * HPIT + acol]);
    unsigned kA[2][4], vAb[2][8];
#pragma unroll
    for (int b = 0; b < 2; b++) {
#pragma unroll
        for (int p = 0; p < 4; p++)
            kA[b][p] = smem_u32(&Ks[b * KVH + (p * 16 + brow) * HPIT + bcol]);
#pragma unroll
        for (int p = 0; p < 8; p++)
            vAb[b][p] = smem_u32(&Vs[b * KVH + vrow * HPIT + p * 16 + vcol]);
    }
    const unsigned qsB = smem_u32(Qs);
    const unsigned ksB0 = smem_u32(Ks);
    const unsigned ksB1 = smem_u32(Ks + KVH);
    const unsigned vsB0 = smem_u32(Vs);
    const unsigned vsB1 = smem_u32(Vs + KVH);

    // load Q tile: 128 rows x 256 B
    const __half* qg = g_qkvh + (size_t)qbase * QKV_N + h * HD;
#pragma unroll
    for (int j = 0; j < 8; j++) {
        int f = tid + 256 * j;
        int row = f >> 4, seg = (f & 15) << 4;
        CP16(qsB + (unsigned)(row * 272 + seg),
             (const char*)(qg + (size_t)row * QKV_N) + seg);
    }
    // K0, V0: 64 rows x 256 B each
    {
        const __half* kg = g_qkvh + 2048 + h * HD;
        const __half* vg = g_qkvh + 4096 + h * HD;
#pragma unroll
        for (int j = 0; j < 4; j++) {
            int f = tid + 256 * j;
            int row = f >> 4, seg = (f & 15) << 4;
            CP16(ksB0 + (unsigned)(row * 272 + seg),
                 (const char*)(kg + (size_t)row * QKV_N) + seg);
            CP16(vsB0 + (unsigned)(row * 272 + seg),
                 (const char*)(vg + (size_t)row * QKV_N) + seg);
        }
    }
    CPCOMMIT();

    float oacc[16][4];
#pragma unroll
    for (int nd = 0; nd < 16; nd++)
#pragma unroll
        for (int c = 0; c < 4; c++) oacc[nd][c] = 0.0f;

    float m0 = -INFINITY, m1 = -INFINITY, l0 = 0.0f, l1 = 0.0f;
    const int row0 = qbase + rw + g;
    const int row1 = row0 + 8;

    CPWAIT0();
    __syncthreads();

    const int nkv = 2 * qt + 2;
    for (int kb = 0; kb < nkv; kb++) {
        const int buf = kb & 1;
        const bool pre = (kb + 1 < nkv);

        if (pre) {
            const __half* kg = g_qkvh + (size_t)((kb + 1) * 64) * QKV_N + 2048 + h * HD;
            const __half* vg = g_qkvh + (size_t)((kb + 1) * 64) * QKV_N + 4096 + h * HD;
            const unsigned kd = buf ? ksB0 : ksB1;
            const unsigned vd = buf ? vsB0 : vsB1;
#pragma unroll
            for (int j = 0; j < 4; j++) {
                int f = tid + 256 * j;
                int row = f >> 4, seg = (f & 15) << 4;
                CP16(kd + (unsigned)(row * 272 + seg),
                     (const char*)(kg + (size_t)row * QKV_N) + seg);
                CP16(vd + (unsigned)(row * 272 + seg),
                     (const char*)(vg + (size_t)row * QKV_N) + seg);
            }
        }
        CPCOMMIT();

        // ---- S = Q K^T ----
        float sacc[8][4];
#pragma unroll
        for (int ni = 0; ni < 8; ni++)
#pragma unroll
            for (int c = 0; c < 4; c++) sacc[ni][c] = 0.0f;

#pragma unroll
        for (int kk = 0; kk < 8; kk++) {
            unsigned a[4], kf[4];
            ldsm4u(a, qAddr + kk * 32);
#pragma unroll
            for (int p = 0; p < 4; p++) {
                ldsm4u(kf, kA[buf][p] + kk * 32);
                mma_f16(sacc[2 * p],     a, &kf[0]);
                mma_f16(sacc[2 * p + 1], a, &kf[2]);
            }
        }

        // ---- softmax (warp-local) ----
        const bool needmask = (kb >= 2 * qt);
        float rmax0 = -INFINITY, rmax1 = -INFINITY;
#pragma unroll
        for (int ni = 0; ni < 8; ni++) {
            int c0 = kb * 64 + ni * 8 + 2 * tig;
            float v0 = sacc[ni][0] * ATTN_SCALE;
            float v1 = sacc[ni][1] * ATTN_SCALE;
            float v2 = sacc[ni][2] * ATTN_SCALE;
            float v3 = sacc[ni][3] * ATTN_SCALE;
            if (needmask) {
                if (c0     > row0) v0 = -INFINITY;
                if (c0 + 1 > row0) v1 = -INFINITY;
                if (c0     > row1) v2 = -INFINITY;
                if (c0 + 1 > row1) v3 = -INFINITY;
            }
            sacc[ni][0] = v0; sacc[ni][1] = v1;
            sacc[ni][2] = v2; sacc[ni][3] = v3;
            rmax0 = fmaxf(rmax0, fmaxf(v0, v1));
            rmax1 = fmaxf(rmax1, fmaxf(v2, v3));
        }
        rmax0 = fmaxf(rmax0, __shfl_xor_sync(0xffffffffu, rmax0, 1));
        rmax0 = fmaxf(rmax0, __shfl_xor_sync(0xffffffffu, rmax0, 2));
        rmax1 = fmaxf(rmax1, __shfl_xor_sync(0xffffffffu, rmax1, 1));
        rmax1 = fmaxf(rmax1, __shfl_xor_sync(0xffffffffu, rmax1, 2));

        float mn0 = fmaxf(m0, rmax0);
        float mn1 = fmaxf(m1, rmax1);
        float fr0 = __expf(m0 - mn0);
        float fr1 = __expf(m1 - mn1);
        m0 = mn0; m1 = mn1;

        unsigned pA[8], pB[8];
        float sum0 = 0.0f, sum1 = 0.0f;
#pragma unroll
        for (int ni = 0; ni < 8; ni++) {
            float p0 = __expf(sacc[ni][0] - mn0);
            float p1 = __expf(sacc[ni][1] - mn0);
            float p2 = __expf(sacc[ni][2] - mn1);
            float p3 = __expf(sacc[ni][3] - mn1);
            sum0 += p0 + p1;
            sum1 += p2 + p3;
            pA[ni] = h2u(__floats2half2_rn(p0, p1));
            pB[ni] = h2u(__floats2half2_rn(p2, p3));
        }
        sum0 += __shfl_xor_sync(0xffffffffu, sum0, 1);
        sum0 += __shfl_xor_sync(0xffffffffu, sum0, 2);
        sum1 += __shfl_xor_sync(0xffffffffu, sum1, 1);
        sum1 += __shfl_xor_sync(0xffffffffu, sum1, 2);
        l0 = l0 * fr0 + sum0;
        l1 = l1 * fr1 + sum1;

#pragma unroll
        for (int nd = 0; nd < 16; nd++) {
            oacc[nd][0] *= fr0; oacc[nd][1] *= fr0;
            oacc[nd][2] *= fr1; oacc[nd][3] *= fr1;
        }

        // ---- O += P V (ldmatrix.trans; P already in A layout) ----
#pragma unroll
        for (int sc = 0; sc < 4; sc++) {
            unsigned a[4];
            a[0] = pA[2 * sc];
            a[1] = pB[2 * sc];
            a[2] = pA[2 * sc + 1];
            a[3] = pB[2 * sc + 1];
            const unsigned scOff = (unsigned)(sc * 16 * 272);
#pragma unroll
            for (int p = 0; p < 8; p++) {
                unsigned vf[4];
                ldsm4t(vf, vAb[buf][p] + scOff);
                mma_f16(oacc[2 * p],     a, &vf[0]);
                mma_f16(oacc[2 * p + 1], a, &vf[2]);
            }
        }

        CPWAIT0();
        __syncthreads();
    }

    // epilogue: normalize, emit fp16 y
    const float inv0 = 1.0f / l0;
    const float inv1 = 1.0f / l1;
    __half* dst0 = g_yh + (size_t)row0 * DIM_C + h * HD;
    __half* dst1 = g_yh + (size_t)row1 * DIM_C + h * HD;
#pragma unroll
    for (int nd = 0; nd < 16; nd++) {
        int col = nd * 8 + 2 * tig;
        *(__half2*)&dst0[col] =
            __floats2half2_rn(oacc[nd][0] * inv0, oacc[nd][1] * inv0);
        *(__half2*)&dst1[col] =
            __floats2half2_rn(oacc[nd][2] * inv1, oacc[nd][3] * inv1);
    }
}

// ---------------------------------------------------------------------------
extern "C" void kernel_launch(void* const* d_in, const int* in_sizes, int n_in,
                              void* d_out, int out_size)
{
    const float* x   = (const float*)d_in[0];   // [1,2048,2048]
    const float* w   = (const float*)d_in[1];   // [4,2048,2048]
    const float* ve  = (const float*)d_in[2];   // [1,2048,2048]
    const float* lam = (const float*)d_in[3];   // [2]
    float* out = (float*)d_out;                 // [1,2048,2048] f32

    __half *xh_ptr = nullptr, *wh_ptr = nullptr, *yh_ptr = nullptr;
    cudaGetSymbolAddress((void**)&xh_ptr, g_xh);
    cudaGetSymbolAddress((void**)&wh_ptr, g_wh);
    cudaGetSymbolAddress((void**)&yh_ptr, g_yh);

    // 0) convert x, w to fp16
    to_half_kernel<<<2048, 256>>>((const float4*)x, (__half2*)xh_ptr,
                                  T_SEQ * DIM_C / 4);
    to_half_kernel<<<4096, 256>>>((const float4*)w, (__half2*)wh_ptr,
                                  4 * DIM_C * DIM_C / 4);

    cudaFuncSetAttribute(gemm_f16_kernel,
                         cudaFuncAttributeMaxDynamicSharedMemorySize, GEMM_SMEM);

    // 1) QKV projection (fp16 mma) + fused RMSNorm/RoPE/v-blend -> g_qkvh
    gemm_f16_kernel<<<dim3(48, 16), 256, GEMM_SMEM>>>(
        xh_ptr, wh_ptr, nullptr, 2048, 6144, 2048, 1, ve, lam);

    // 2) causal attention (fp16 mma; writes fp16 y)
    cudaFuncSetAttribute(attn_kernel,
                         cudaFuncAttributeMaxDynamicSharedMemorySize, ATTN_SMEMH);
    attn_kernel<<<dim3(16, 16), 256, ATTN_SMEMH>>>();

    // 3) output projection (fp16 mma)
    gemm_f16_kernel<<<dim3(16, 16), 256, GEMM_SMEM>>>(
        yh_ptr, wh_ptr + (size_t)3 * DIM_C * DIM_C, out, 2048, 2048, 2048,
        0, nullptr, nullptr);
}